// round 3
// baseline (speedup 1.0000x reference)
#include <cuda_runtime.h>

// ---------------------------------------------------------------------------
// XNOR-net CNN forward, GB300. All binary convs computed exactly via bitpack +
// popcount. Intermediates are 1-bit tensors in __device__ globals (no allocs).
// ---------------------------------------------------------------------------

// Bit tensors: layout [b][y][x][cw], bit j of word cw = channel cw*32+j (1 = positive)
__device__ unsigned g_bits1[128 * 32 * 32 * 4];   // conv1 out signs (128 ch)
__device__ unsigned g_bits2[128 * 16 * 16 * 4];   // after conv2+pool+bn (128 ch)
__device__ unsigned g_bits3[128 * 16 * 16 * 8];   // after conv3+bn (256 ch)
__device__ unsigned g_bits4[128 * 8 * 8 * 8];     // after conv4+pool+bn (256 ch)
__device__ unsigned g_bits5[128 * 8 * 8 * 16];    // after conv5+bn (512 ch)
__device__ float    g_h6[128 * 4 * 4 * 512];      // after conv6+pool+bn (float)

// Packed weights: layout [tap(9)][cin_word][cout], bit j = cin cw*32+j
__device__ unsigned g_pw2[9 * 4 * 128];
__device__ unsigned g_pw3[9 * 4 * 256];
__device__ unsigned g_pw4[9 * 8 * 256];
__device__ unsigned g_pw5[9 * 8 * 512];
__device__ unsigned g_pw6[9 * 16 * 512];

// ---------------------------------------------------------------------------
// Weight bit-packing: w is HWIO float [3][3][Cin][Cout]
// ---------------------------------------------------------------------------
__global__ void pack_weights_kernel(const float* __restrict__ w, int Cin, int Cout, int which)
{
    unsigned* out = (which == 2) ? g_pw2 : (which == 3) ? g_pw3 :
                    (which == 4) ? g_pw4 : (which == 5) ? g_pw5 : g_pw6;
    int cwn = Cin >> 5;
    int n = 9 * cwn * Cout;
    int idx = blockIdx.x * 256 + threadIdx.x;
    if (idx >= n) return;
    int co = idx % Cout;
    int q = idx / Cout;            // q = t*cwn + cw
    int cw = q % cwn;
    int t = q / cwn;
    unsigned word = 0;
    for (int j = 0; j < 32; j++) {
        float v = w[(t * Cin + cw * 32 + j) * Cout + co];
        word |= (v > 0.f ? 1u : 0u) << j;
    }
    out[q * Cout + co] = word;
}

// ---------------------------------------------------------------------------
// conv1: fp32 3x3 conv 3->128 SAME, +b1, relu, BN, sign -> bitpack
// One thread per pixel, computes all 128 output channels in 4x32 chunks.
// ---------------------------------------------------------------------------
__global__ void __launch_bounds__(128) conv1_kernel(
    const float* __restrict__ x, const float* __restrict__ w1,
    const float* __restrict__ b1, const float* __restrict__ s1,
    const float* __restrict__ bi1)
{
    __shared__ __align__(16) float sw[27 * 128];
    __shared__ float sb[128], ss[128], sbi[128];
    int tid = threadIdx.x;
    for (int i = tid; i < 27 * 128; i += 128) sw[i] = w1[i]; // same flat layout
    sb[tid] = b1[tid];
    ss[tid] = s1[tid];
    sbi[tid] = bi1[tid];
    __syncthreads();

    int pid = blockIdx.x * 128 + tid;      // 0..131071
    int b = pid >> 10;
    int y = (pid >> 5) & 31;
    int xx = pid & 31;

    float in[27];
#pragma unroll
    for (int dy = 0; dy < 3; dy++)
#pragma unroll
        for (int dx = 0; dx < 3; dx++) {
            int iy = y + dy - 1, ix = xx + dx - 1;
            bool v = (iy >= 0 && iy < 32 && ix >= 0 && ix < 32);
            const float* p = x + ((b * 32 + iy) * 32 + ix) * 3;
#pragma unroll
            for (int c = 0; c < 3; c++)
                in[(dy * 3 + dx) * 3 + c] = v ? p[c] : 0.f;
        }

#pragma unroll
    for (int chunk = 0; chunk < 4; chunk++) {
        unsigned word = 0;
#pragma unroll
        for (int jj = 0; jj < 8; jj++) {
            int co4 = chunk * 32 + jj * 4;
            float4 acc = make_float4(0.f, 0.f, 0.f, 0.f);
#pragma unroll
            for (int k = 0; k < 27; k++) {
                float4 wv = *reinterpret_cast<const float4*>(&sw[k * 128 + co4]);
                float iv = in[k];
                acc.x = fmaf(iv, wv.x, acc.x);
                acc.y = fmaf(iv, wv.y, acc.y);
                acc.z = fmaf(iv, wv.z, acc.z);
                acc.w = fmaf(iv, wv.w, acc.w);
            }
            float av[4] = {acc.x, acc.y, acc.z, acc.w};
#pragma unroll
            for (int e = 0; e < 4; e++) {
                int co = co4 + e;
                float v = fmaxf(av[e] + sb[co], 0.f);
                bool bit = fmaf(v, ss[co], sbi[co]) > 0.f;
                word |= (bit ? 1u : 0u) << (jj * 4 + e);
            }
        }
        g_bits1[pid * 4 + chunk] = word;
    }
}

// ---------------------------------------------------------------------------
// Binary conv: xnor-popcount with zero halo + weight-sign border correction.
// Warp = 32 consecutive output channels (lane = co). 8 warps split pixels.
// ---------------------------------------------------------------------------
__device__ __forceinline__ int border_corr(int y, int x, int H, int W, const int S[9])
{
    int c = 0;
    if (y == 0)      c += S[0] + S[1] + S[2];
    if (y == H - 1)  c += S[6] + S[7] + S[8];
    if (x == 0) {
        c += S[0] + S[3] + S[6];
        if (y == 0)     c -= S[0];
        if (y == H - 1) c -= S[6];
    }
    if (x == W - 1) {
        c += S[2] + S[5] + S[8];
        if (y == 0)     c -= S[2];
        if (y == H - 1) c -= S[8];
    }
    return c;
}

template <int H, int W, int CW, int COUT, bool POOL, int LAYER>
__global__ void __launch_bounds__(256) bconv_kernel(
    const float* __restrict__ bn_s, const float* __restrict__ bn_b)
{
    constexpr int CIN = CW * 32;
    constexpr int OH = POOL ? H / 2 : H;
    constexpr int OW = POOL ? W / 2 : W;
    constexpr int COW = COUT / 32;
    constexpr bool FINAL = (LAYER == 6);

    const unsigned* in_bits;
    const unsigned* wp;
    unsigned* outb = nullptr;
    if constexpr (LAYER == 2) { in_bits = g_bits1; wp = g_pw2; outb = g_bits2; }
    else if constexpr (LAYER == 3) { in_bits = g_bits2; wp = g_pw3; outb = g_bits3; }
    else if constexpr (LAYER == 4) { in_bits = g_bits3; wp = g_pw4; outb = g_bits4; }
    else if constexpr (LAYER == 5) { in_bits = g_bits4; wp = g_pw5; outb = g_bits5; }
    else { in_bits = g_bits5; wp = g_pw6; }

    __shared__ unsigned act[(H + 2) * (W + 2) * CW];
    __shared__ unsigned wsm[9 * CW * 32];

    const int tid = threadIdx.x, lane = tid & 31, warp = tid >> 5;
    const int b = blockIdx.y, cog = blockIdx.x;
    const int co = cog * 32 + lane;

    // activation bits -> smem with zero halo
    for (int i = tid; i < (H + 2) * (W + 2) * CW; i += 256) {
        int cw = i % CW;
        int q = i / CW;
        int xx = q % (W + 2);
        int yy = q / (W + 2);
        unsigned v = 0;
        if (yy >= 1 && yy <= H && xx >= 1 && xx <= W)
            v = in_bits[((b * H + (yy - 1)) * W + (xx - 1)) * CW + cw];
        act[i] = v;
    }
    // weight bits for this block's 32 output channels
    for (int i = tid; i < 9 * CW * 32; i += 256) {
        int l = i & 31;
        int q = i >> 5;                       // t*CW + cw
        wsm[i] = wp[q * COUT + cog * 32 + l];
    }
    __syncthreads();

    // per-tap weight sign sums (for border correction)
    int S[9];
#pragma unroll
    for (int t = 0; t < 9; t++) {
        int p = 0;
#pragma unroll
        for (int cw = 0; cw < CW; cw++) p += __popc(wsm[(t * CW + cw) * 32 + lane]);
        S[t] = CIN - 2 * p;
    }
    const float scale = bn_s[co], bias = bn_b[co];

    for (int op = warp; op < OH * OW; op += 8) {
        const int oy = op / OW, ox = op % OW;
        if constexpr (POOL) {
            int acc0 = 0, acc1 = 0, acc2 = 0, acc3 = 0;
            const int iy = 2 * oy, ix = 2 * ox;  // halo-space base row/col
            for (int cw = 0; cw < CW; cw++) {
                unsigned wv[9];
#pragma unroll
                for (int t = 0; t < 9; t++) wv[t] = wsm[(t * CW + cw) * 32 + lane];
                unsigned a[16];
#pragma unroll
                for (int r = 0; r < 4; r++)
#pragma unroll
                    for (int c = 0; c < 4; c++)
                        a[r * 4 + c] = act[((iy + r) * (W + 2) + (ix + c)) * CW + cw];
#pragma unroll
                for (int dy = 0; dy < 3; dy++)
#pragma unroll
                    for (int dx = 0; dx < 3; dx++) {
                        unsigned w = wv[dy * 3 + dx];
                        acc0 += __popc(a[dy * 4 + dx] ^ w);
                        acc1 += __popc(a[dy * 4 + dx + 1] ^ w);
                        acc2 += __popc(a[(dy + 1) * 4 + dx] ^ w);
                        acc3 += __popc(a[(dy + 1) * 4 + dx + 1] ^ w);
                    }
            }
            int s0 = 9 * CIN - 2 * acc0 - border_corr(2 * oy, 2 * ox, H, W, S);
            int s1 = 9 * CIN - 2 * acc1 - border_corr(2 * oy, 2 * ox + 1, H, W, S);
            int s2 = 9 * CIN - 2 * acc2 - border_corr(2 * oy + 1, 2 * ox, H, W, S);
            int s3 = 9 * CIN - 2 * acc3 - border_corr(2 * oy + 1, 2 * ox + 1, H, W, S);
            int m = max(0, max(max(s0, s1), max(s2, s3)));  // relu then maxpool
            if constexpr (FINAL) {
                g_h6[((b * OH + oy) * OW + ox) * COUT + co] = fmaf((float)m, scale, bias);
            } else {
                bool bit = fmaf((float)m, scale, bias) > 0.f;
                unsigned wd = __ballot_sync(0xffffffffu, bit);
                if (lane == 0) outb[((b * OH + oy) * OW + ox) * COW + cog] = wd;
            }
        } else {
            int acc = 0;
            for (int cw = 0; cw < CW; cw++) {
                unsigned wv[9];
#pragma unroll
                for (int t = 0; t < 9; t++) wv[t] = wsm[(t * CW + cw) * 32 + lane];
                unsigned a[9];
#pragma unroll
                for (int r = 0; r < 3; r++)
#pragma unroll
                    for (int c = 0; c < 3; c++)
                        a[r * 3 + c] = act[((oy + r) * (W + 2) + (ox + c)) * CW + cw];
#pragma unroll
                for (int t = 0; t < 9; t++) acc += __popc(a[t] ^ wv[t]);
            }
            int s = 9 * CIN - 2 * acc - border_corr(oy, ox, H, W, S);
            int m = max(s, 0);
            bool bit = fmaf((float)m, scale, bias) > 0.f;
            unsigned wd = __ballot_sync(0xffffffffu, bit);
            if (lane == 0) outb[((b * OH + oy) * OW + ox) * COW + cog] = wd;
        }
    }
}

// ---------------------------------------------------------------------------
// Dense (512->10 on last axis) + bias + softmax. One thread per (b,h,w) row.
// ---------------------------------------------------------------------------
__global__ void __launch_bounds__(128) dense_softmax_kernel(
    const float* __restrict__ dw, const float* __restrict__ db, float* __restrict__ out)
{
    __shared__ float sdw[512 * 10];
    __shared__ float sdb[10];
    int tid = threadIdx.x;
    for (int i = tid; i < 5120; i += 128) sdw[i] = dw[i];
    if (tid < 10) sdb[tid] = db[tid];
    __syncthreads();

    int r = blockIdx.x * 128 + tid;   // 0..2047
    float acc[10];
#pragma unroll
    for (int d = 0; d < 10; d++) acc[d] = sdb[d];
    const float* h = g_h6 + r * 512;
    for (int c = 0; c < 512; c++) {
        float hv = h[c];
#pragma unroll
        for (int d = 0; d < 10; d++) acc[d] = fmaf(hv, sdw[c * 10 + d], acc[d]);
    }
    float m = acc[0];
#pragma unroll
    for (int d = 1; d < 10; d++) m = fmaxf(m, acc[d]);
    float e[10], s = 0.f;
#pragma unroll
    for (int d = 0; d < 10; d++) { e[d] = expf(acc[d] - m); s += e[d]; }
    float inv = 1.f / s;
#pragma unroll
    for (int d = 0; d < 10; d++) out[r * 10 + d] = e[d] * inv;
}

// ---------------------------------------------------------------------------
// Launch. Inputs identified by size (robust to metadata vs signature order):
// sizes: x=393216, w1=3456, b1=128(idx 2), w2=147456, w3=294912, w4=589824,
// w5=1179648, w6=2359296, dense_w=5120, dense_b=10; remaining 12 are bn
// params in order bn1_scale, bn1_bias, ..., bn6_scale, bn6_bias.
// ---------------------------------------------------------------------------
extern "C" void kernel_launch(void* const* d_in, const int* in_sizes, int n_in,
                              void* d_out, int out_size)
{
    const float *x = nullptr, *w1 = nullptr, *b1 = nullptr;
    const float *w2 = nullptr, *w3 = nullptr, *w4 = nullptr, *w5 = nullptr, *w6 = nullptr;
    const float *dw = nullptr, *db = nullptr;
    const float* bns[12] = {nullptr};
    int bn_idx = 0;

    for (int i = 0; i < n_in; i++) {
        const float* p = (const float*)d_in[i];
        int s = in_sizes[i];
        if (i == 0)              x = p;
        else if (s == 3456)      w1 = p;
        else if (i == 2)         b1 = p;
        else if (s == 147456)    w2 = p;
        else if (s == 294912)    w3 = p;
        else if (s == 589824)    w4 = p;
        else if (s == 1179648)   w5 = p;
        else if (s == 2359296)   w6 = p;
        else if (s == 5120)      dw = p;
        else if (s == 10)        db = p;
        else if (bn_idx < 12)    bns[bn_idx++] = p;
    }
    const float *bn2s = bns[2], *bn2b = bns[3];
    const float *bn3s = bns[4], *bn3b = bns[5];
    const float *bn4s = bns[6], *bn4b = bns[7];
    const float *bn5s = bns[8], *bn5b = bns[9];
    const float *bn6s = bns[10], *bn6b = bns[11];

    // pack binary-conv weights
    pack_weights_kernel<<<(9 * 4 * 128 + 255) / 256, 256>>>(w2, 128, 128, 2);
    pack_weights_kernel<<<(9 * 4 * 256 + 255) / 256, 256>>>(w3, 128, 256, 3);
    pack_weights_kernel<<<(9 * 8 * 256 + 255) / 256, 256>>>(w4, 256, 256, 4);
    pack_weights_kernel<<<(9 * 8 * 512 + 255) / 256, 256>>>(w5, 256, 512, 5);
    pack_weights_kernel<<<(9 * 16 * 512 + 255) / 256, 256>>>(w6, 512, 512, 6);

    // conv1 (float) fused with relu+bn1+sign
    conv1_kernel<<<1024, 128>>>(x, w1, b1, bns[0], bns[1]);

    // binary conv chain
    bconv_kernel<32, 32, 4, 128, true, 2><<<dim3(4, 128), 256>>>(bn2s, bn2b);
    bconv_kernel<16, 16, 4, 256, false, 3><<<dim3(8, 128), 256>>>(bn3s, bn3b);
    bconv_kernel<16, 16, 8, 256, true, 4><<<dim3(8, 128), 256>>>(bn4s, bn4b);
    bconv_kernel<8, 8, 8, 512, false, 5><<<dim3(16, 128), 256>>>(bn5s, bn5b);
    bconv_kernel<8, 8, 16, 512, true, 6><<<dim3(16, 128), 256>>>(bn6s, bn6b);

    // dense + softmax
    dense_softmax_kernel<<<16, 128>>>(dw, db, (float*)d_out);
    (void)out_size;
}